// round 4
// baseline (speedup 1.0000x reference)
#include <cuda_runtime.h>

#define ROWS 33
#define NTHREADS 256

__global__ __launch_bounds__(NTHREADS, 3)
void matcher_cost_kernel4(const float* __restrict__ logits,   // [BN, C]
                          const float* __restrict__ pboxes,   // [BN, 4] cxcywh
                          const int*   __restrict__ tlabw,    // T labels (int32 or int64 words)
                          const float* __restrict__ tboxes,   // [T, 4] raw (used as-is)
                          float* __restrict__ out,            // [BN, T]
                          int BN, int C, int T)
{
    extern __shared__ float sm[];
    float*  sprob = sm;                                   // ROWS * C  (stores 5 - p)
    int prob_off = (ROWS * C + 3) & ~3;                   // 16B align
    float4* srow  = (float4*)(sm + prob_off);             // ROWS * 3 float4

    const int tid  = threadIdx.x;
    const int row0 = blockIdx.x * ROWS;

    // ---- detect int64 vs int32 label storage (odd 32-bit words all zero) ----
    bool is64 = false;
    if (T >= 8) {
        is64 = (tlabw[1] == 0) & (tlabw[3] == 0) & (tlabw[5] == 0) & (tlabw[7] == 0) &
               (tlabw[9] == 0) & (tlabw[11] == 0) & (tlabw[13] == 0) & (tlabw[15] == 0);
    }

    // ---- per-row prediction-box constants (12 floats each, 3 float4) ----
    if (tid < ROWS) {
        int row = row0 + tid;
        if (row < BN) {
            float4 b = ((const float4*)pboxes)[row];
            float px0 = b.x - 0.5f * b.z, py0 = b.y - 0.5f * b.w;
            float px1 = b.x + 0.5f * b.z, py1 = b.y + 0.5f * b.w;
            srow[tid * 3 + 0] = b;                                  // cx cy pw ph
            srow[tid * 3 + 1] = make_float4(px0, py0, px1, py1);
            srow[tid * 3 + 2] = make_float4((px1 - px0) * (py1 - py0), 0.f, 0.f, 0.f);
        }
    }

    // ---- softmax (one warp per row, strided); store 5 - p ----
    {
        int warp = tid >> 5, lane = tid & 31;
        for (int lr = warp; lr < ROWS; lr += NTHREADS / 32) {
            int row = row0 + lr;
            if (row >= BN) continue;
            const float* lg = logits + (size_t)row * C;
            float m = -3.4e38f;
            for (int c = lane; c < C; c += 32) m = fmaxf(m, __ldg(lg + c));
#pragma unroll
            for (int o = 16; o; o >>= 1) m = fmaxf(m, __shfl_xor_sync(0xFFFFFFFFu, m, o));
            float s = 0.f;
            float* pr = sprob + lr * C;
            for (int c = lane; c < C; c += 32) {
                float e = __expf(__ldg(lg + c) - m);
                s += e;
                pr[c] = e;
            }
#pragma unroll
            for (int o = 16; o; o >>= 1) s += __shfl_xor_sync(0xFFFFFFFFu, s, o);
            float ninv = -1.0f / s;
            for (int c = lane; c < C; c += 32) pr[c] = fmaf(pr[c], ninv, 5.0f);
        }
    }
    __syncthreads();

    const int rows_here = min(ROWS, BN - row0);
    const float4* tb4 = (const float4*)tboxes;

    // ---- each thread owns 4 targets in registers, loops over rows ----
    for (int tb0 = 4 * tid; tb0 < T; tb0 += 4 * NTHREADS) {
        int nv = min(4, T - tb0);
        bool full = (nv == 4);

        float4 t[4];
        float  twd[4], thd[4], ta2[4];
        int    lb[4];
#pragma unroll
        for (int j = 0; j < 4; ++j) {
            if (j < nv) {
                t[j]  = tb4[tb0 + j];
                lb[j] = is64 ? tlabw[2 * (tb0 + j)] : tlabw[tb0 + j];
            } else {
                t[j]  = make_float4(0.f, 0.f, 1.f, 1.f);
                lb[j] = 0;
            }
            twd[j] = t[j].z - t[j].x;   // target "width"  (xyxy interp)
            thd[j] = t[j].w - t[j].y;   // target "height"
            ta2[j] = twd[j] * thd[j];   // target area
        }

        float* optr = out + (size_t)row0 * T + tb0;
        const float* pr = sprob;
        for (int r = 0; r < rows_here; ++r, optr += T, pr += C) {
            float4 c0 = srow[r * 3 + 0];     // cx cy pw ph
            float4 c1 = srow[r * 3 + 1];     // px0 py0 px1 py1
            float  pa = srow[r * 3 + 2].x;

            float4 res;
#pragma unroll
            for (int j = 0; j < 4; ++j) {
                float tx = t[j].x, ty = t[j].y, tz = t[j].z, tw = t[j].w;
                float base = pr[lb[j]];                          // 5 - p
                float l1 = fabsf(c0.x - tx) + fabsf(c0.y - ty)
                         + fabsf(c0.z - tz) + fabsf(c0.w - tw);
                float iw = fminf(c1.z, tz) - fmaxf(c1.x, tx);
                float ih = fminf(c1.w, tw) - fmaxf(c1.y, ty);
                float inter = fmaxf(iw, 0.f) * fmaxf(ih, 0.f);
                // enclosing box via min+max = a+b identity:
                float ew = (c0.z + twd[j]) - iw;                 // pw + twd - iw
                float eh = (c0.w + thd[j]) - ih;                 // ph + thd - ih
                float ae = ew * eh;
                float uni = (pa + ta2[j]) - inter;
                float q  = __fdividef(fmaf(uni, uni, inter * ae), uni * ae);
                (&res.x)[j] = fmaf(-2.f, q, fmaf(5.f, l1, base));
            }
            if (full) {
                *(float4*)optr = res;
            } else {
#pragma unroll
                for (int j = 0; j < 4; ++j)
                    if (j < nv) optr[j] = (&res.x)[j];
            }
        }
    }
}

extern "C" void kernel_launch(void* const* d_in, const int* in_sizes, int n_in,
                              void* d_out, int out_size)
{
    const float* logits = (const float*)d_in[0];   // out_labels [B,N,C]
    const float* pboxes = (const float*)d_in[1];   // out_bboxes [B,N,4]
    const int*   tlabw  = (const int*)d_in[2];     // tgt_labels [T] (int32 or int64)
    const float* tboxes = (const float*)d_in[3];   // tgt_bboxes [T,4]
    float* out = (float*)d_out;

    int BN = in_sizes[1] / 4;
    int C  = in_sizes[0] / BN;
    int T  = in_sizes[2];

    int prob_off = (ROWS * C + 3) & ~3;
    size_t smem = (size_t)(prob_off + ROWS * 12) * sizeof(float) + 16;

    int grid = (BN + ROWS - 1) / ROWS;
    matcher_cost_kernel4<<<grid, NTHREADS, smem>>>(logits, pboxes, tlabw, tboxes,
                                                   out, BN, C, T);
}

// round 5
// speedup vs baseline: 1.0077x; 1.0077x over previous
#include <cuda_runtime.h>

#define ROWS 33
#define NTHREADS 256

__device__ __forceinline__ float rcp_approx(float x) {
    float r;
    asm("rcp.approx.f32 %0, %1;" : "=f"(r) : "f"(x));
    return r;
}

__global__ __launch_bounds__(NTHREADS, 3)
void matcher_cost_kernel5(const float* __restrict__ logits,   // [BN, C]
                          const float* __restrict__ pboxes,   // [BN, 4] cxcywh
                          const int*   __restrict__ tlabw,    // T labels (int32 or int64 words)
                          const float* __restrict__ tboxes,   // [T, 4] raw (used as-is)
                          float* __restrict__ out,            // [BN, T]
                          int BN, int C, int T)
{
    extern __shared__ float sm[];
    float*  sprob = sm;                                   // ROWS * C  (stores 5 - p)
    int prob_off = (ROWS * C + 3) & ~3;                   // 16B align
    float4* srow  = (float4*)(sm + prob_off);             // ROWS * 3 float4

    const int tid  = threadIdx.x;
    const int row0 = blockIdx.x * ROWS;

    // ---- detect int64 vs int32 label storage (odd 32-bit words all zero) ----
    bool is64 = false;
    if (T >= 8) {
        is64 = (tlabw[1] == 0) & (tlabw[3] == 0) & (tlabw[5] == 0) & (tlabw[7] == 0) &
               (tlabw[9] == 0) & (tlabw[11] == 0) & (tlabw[13] == 0) & (tlabw[15] == 0);
    }

    // ---- per-row prediction-box constants (12 floats each, 3 float4) ----
    if (tid < ROWS) {
        int row = row0 + tid;
        if (row < BN) {
            float4 b = ((const float4*)pboxes)[row];
            float px0 = b.x - 0.5f * b.z, py0 = b.y - 0.5f * b.w;
            float px1 = b.x + 0.5f * b.z, py1 = b.y + 0.5f * b.w;
            srow[tid * 3 + 0] = b;                                  // cx cy pw ph
            srow[tid * 3 + 1] = make_float4(px0, py0, px1, py1);
            srow[tid * 3 + 2] = make_float4((px1 - px0) * (py1 - py0), 0.f, 0.f, 0.f);
        }
    }

    // ---- softmax (one warp per row, strided); store 5 - p ----
    {
        int warp = tid >> 5, lane = tid & 31;
        for (int lr = warp; lr < ROWS; lr += NTHREADS / 32) {
            int row = row0 + lr;
            if (row >= BN) continue;
            const float* lg = logits + (size_t)row * C;
            float m = -3.4e38f;
            for (int c = lane; c < C; c += 32) m = fmaxf(m, __ldg(lg + c));
#pragma unroll
            for (int o = 16; o; o >>= 1) m = fmaxf(m, __shfl_xor_sync(0xFFFFFFFFu, m, o));
            float s = 0.f;
            float* pr = sprob + lr * C;
            for (int c = lane; c < C; c += 32) {
                float e = __expf(__ldg(lg + c) - m);
                s += e;
                pr[c] = e;
            }
#pragma unroll
            for (int o = 16; o; o >>= 1) s += __shfl_xor_sync(0xFFFFFFFFu, s, o);
            float ninv = -1.0f / s;
            for (int c = lane; c < C; c += 32) pr[c] = fmaf(pr[c], ninv, 5.0f);
        }
    }
    __syncthreads();

    const int rows_here = min(ROWS, BN - row0);
    const float4* tb4 = (const float4*)tboxes;

    // ---- each thread owns 4 targets in registers, loops over rows ----
    for (int tb0 = 4 * tid; tb0 < T; tb0 += 4 * NTHREADS) {
        int nv = min(4, T - tb0);
        bool full = (nv == 4);

        float4 t[4];
        float  twd[4], thd[4], ta2[4];
        int    lb[4];
#pragma unroll
        for (int j = 0; j < 4; ++j) {
            if (j < nv) {
                t[j]  = tb4[tb0 + j];
                lb[j] = is64 ? tlabw[2 * (tb0 + j)] : tlabw[tb0 + j];
            } else {
                t[j]  = make_float4(0.f, 0.f, 1.f, 1.f);
                lb[j] = 0;
            }
            twd[j] = t[j].z - t[j].x;   // target "width"  (xyxy interp)
            thd[j] = t[j].w - t[j].y;   // target "height"
            ta2[j] = twd[j] * thd[j];   // target area
        }

        float* optr = out + (size_t)row0 * T + tb0;
        const float* pr = sprob;
        for (int r = 0; r < rows_here; ++r, optr += T, pr += C) {
            float4 c0 = srow[r * 3 + 0];     // cx cy pw ph
            float4 c1 = srow[r * 3 + 1];     // px0 py0 px1 py1
            float  pa = srow[r * 3 + 2].x;

            float num[4], den[4], acc[4];
#pragma unroll
            for (int j = 0; j < 4; ++j) {
                float tx = t[j].x, ty = t[j].y, tz = t[j].z, tw = t[j].w;
                float base = pr[lb[j]];                          // 5 - p
                float l1 = fabsf(c0.x - tx) + fabsf(c0.y - ty)
                         + fabsf(c0.z - tz) + fabsf(c0.w - tw);
                float iw = fminf(c1.z, tz) - fmaxf(c1.x, tx);
                float ih = fminf(c1.w, tw) - fmaxf(c1.y, ty);
                float inter = fmaxf(iw, 0.f) * fmaxf(ih, 0.f);
                // enclosing box via min+max = a+b identity:
                float ew = (c0.z + twd[j]) - iw;                 // pw + twd - iw
                float eh = (c0.w + thd[j]) - ih;                 // ph + thd - ih
                float ae = ew * eh;
                float uni = (pa + ta2[j]) - inter;
                num[j] = fmaf(uni, uni, inter * ae);
                den[j] = uni * ae;
                acc[j] = fmaf(5.f, l1, base);
            }
            // ---- batched reciprocal: 1 MUFU for 4 divisions, -2 folded in ----
            float p01   = den[0] * den[1];
            float p012  = p01 * den[2];
            float p0123 = p012 * den[3];
            float rinv  = -2.f * rcp_approx(p0123);   // carries the -2 weight
            float i012  = rinv * den[3];
            float i3    = rinv * p012;
            float i01   = i012 * den[2];
            float i2    = i012 * p01;
            float i1    = i01  * den[0];
            float i0    = i01  * den[1];

            float4 res;
            res.x = fmaf(num[0], i0, acc[0]);
            res.y = fmaf(num[1], i1, acc[1]);
            res.z = fmaf(num[2], i2, acc[2]);
            res.w = fmaf(num[3], i3, acc[3]);

            if (full) {
                *(float4*)optr = res;
            } else {
#pragma unroll
                for (int j = 0; j < 4; ++j)
                    if (j < nv) optr[j] = (&res.x)[j];
            }
        }
    }
}

extern "C" void kernel_launch(void* const* d_in, const int* in_sizes, int n_in,
                              void* d_out, int out_size)
{
    const float* logits = (const float*)d_in[0];   // out_labels [B,N,C]
    const float* pboxes = (const float*)d_in[1];   // out_bboxes [B,N,4]
    const int*   tlabw  = (const int*)d_in[2];     // tgt_labels [T] (int32 or int64)
    const float* tboxes = (const float*)d_in[3];   // tgt_bboxes [T,4]
    float* out = (float*)d_out;

    int BN = in_sizes[1] / 4;
    int C  = in_sizes[0] / BN;
    int T  = in_sizes[2];

    int prob_off = (ROWS * C + 3) & ~3;
    size_t smem = (size_t)(prob_off + ROWS * 12) * sizeof(float) + 16;

    int grid = (BN + ROWS - 1) / ROWS;
    matcher_cost_kernel5<<<grid, NTHREADS, smem>>>(logits, pboxes, tlabw, tboxes,
                                                   out, BN, C, T);
}

// round 6
// speedup vs baseline: 1.0088x; 1.0011x over previous
#include <cuda_runtime.h>

#define ROWS 33
#define NTHREADS 256

__device__ __forceinline__ float rcp_approx(float x) {
    float r;
    asm("rcp.approx.f32 %0, %1;" : "=f"(r) : "f"(x));
    return r;
}

// Cost for one row against 4 register-resident targets.
__device__ __forceinline__ float4 row_cost4(
    float4 c0, float4 c1, float pa,
    const float4 t[4], const float twd[4], const float thd[4], const int lb[4],
    const float* __restrict__ pr)
{
    float num[4], den[4], acc[4];
#pragma unroll
    for (int j = 0; j < 4; ++j) {
        float tx = t[j].x, ty = t[j].y, tz = t[j].z, tw = t[j].w;
        float base = pr[lb[j]];                          // 5 - p
        float l1 = fabsf(c0.x - tx) + fabsf(c0.y - ty)
                 + fabsf(c0.z - tz) + fabsf(c0.w - tw);
        float iw = fminf(c1.z, tz) - fmaxf(c1.x, tx);
        float ih = fminf(c1.w, tw) - fmaxf(c1.y, ty);
        float inter = fmaxf(iw, 0.f) * fmaxf(ih, 0.f);
        float ew = (c0.z + twd[j]) - iw;                 // pw + twd - iw
        float eh = (c0.w + thd[j]) - ih;                 // ph + thd - ih
        float ae = ew * eh;
        float uni = fmaf(twd[j], thd[j], pa) - inter;    // pa + a2 - inter
        num[j] = fmaf(uni, uni, inter * ae);
        den[j] = uni * ae;
        acc[j] = fmaf(5.f, l1, base);
    }
    // batched reciprocal: 1 MUFU for 4 divisions, -2 weight folded in
    float p01   = den[0] * den[1];
    float p012  = p01 * den[2];
    float p0123 = p012 * den[3];
    float rinv  = -2.f * rcp_approx(p0123);
    float i012  = rinv * den[3];
    float i3    = rinv * p012;
    float i01   = i012 * den[2];
    float i2    = i012 * p01;
    float i1    = i01  * den[0];
    float i0    = i01  * den[1];

    float4 res;
    res.x = fmaf(num[0], i0, acc[0]);
    res.y = fmaf(num[1], i1, acc[1]);
    res.z = fmaf(num[2], i2, acc[2]);
    res.w = fmaf(num[3], i3, acc[3]);
    return res;
}

__global__ __launch_bounds__(NTHREADS, 3)
void matcher_cost_kernel6(const float* __restrict__ logits,   // [BN, C]
                          const float* __restrict__ pboxes,   // [BN, 4] cxcywh
                          const int*   __restrict__ tlabw,    // T labels (int32 or int64 words)
                          const float* __restrict__ tboxes,   // [T, 4] raw (used as-is)
                          float* __restrict__ out,            // [BN, T]
                          int BN, int C, int T)
{
    extern __shared__ float sm[];
    float*  sprob = sm;                                   // ROWS * C  (stores 5 - p)
    int prob_off = (ROWS * C + 3) & ~3;                   // 16B align
    float4* srow  = (float4*)(sm + prob_off);             // ROWS * 3 float4

    const int tid  = threadIdx.x;
    const int row0 = blockIdx.x * ROWS;

    // ---- detect int64 vs int32 label storage (odd 32-bit words all zero) ----
    bool is64 = false;
    if (T >= 8) {
        is64 = (tlabw[1] == 0) & (tlabw[3] == 0) & (tlabw[5] == 0) & (tlabw[7] == 0) &
               (tlabw[9] == 0) & (tlabw[11] == 0) & (tlabw[13] == 0) & (tlabw[15] == 0);
    }

    // ---- per-row prediction-box constants (12 floats each, 3 float4) ----
    if (tid < ROWS) {
        int row = row0 + tid;
        if (row < BN) {
            float4 b = ((const float4*)pboxes)[row];
            float px0 = b.x - 0.5f * b.z, py0 = b.y - 0.5f * b.w;
            float px1 = b.x + 0.5f * b.z, py1 = b.y + 0.5f * b.w;
            srow[tid * 3 + 0] = b;                                  // cx cy pw ph
            srow[tid * 3 + 1] = make_float4(px0, py0, px1, py1);
            srow[tid * 3 + 2] = make_float4((px1 - px0) * (py1 - py0), 0.f, 0.f, 0.f);
        }
    }

    // ---- softmax (one warp per row, strided); store 5 - p ----
    {
        int warp = tid >> 5, lane = tid & 31;
        for (int lr = warp; lr < ROWS; lr += NTHREADS / 32) {
            int row = row0 + lr;
            if (row >= BN) continue;
            const float* lg = logits + (size_t)row * C;
            float m = -3.4e38f;
            for (int c = lane; c < C; c += 32) m = fmaxf(m, __ldg(lg + c));
#pragma unroll
            for (int o = 16; o; o >>= 1) m = fmaxf(m, __shfl_xor_sync(0xFFFFFFFFu, m, o));
            float s = 0.f;
            float* pr = sprob + lr * C;
            for (int c = lane; c < C; c += 32) {
                float e = __expf(__ldg(lg + c) - m);
                s += e;
                pr[c] = e;
            }
#pragma unroll
            for (int o = 16; o; o >>= 1) s += __shfl_xor_sync(0xFFFFFFFFu, s, o);
            float ninv = -1.0f / s;
            for (int c = lane; c < C; c += 32) pr[c] = fmaf(pr[c], ninv, 5.0f);
        }
    }
    __syncthreads();

    const int rows_here = min(ROWS, BN - row0);
    const float4* tb4 = (const float4*)tboxes;

    // ---- each thread owns 4 targets in registers, loops over rows (2x unroll) ----
    for (int tb0 = 4 * tid; tb0 < T; tb0 += 4 * NTHREADS) {
        int nv = min(4, T - tb0);
        bool full = (nv == 4);

        float4 t[4];
        float  twd[4], thd[4];
        int    lb[4];
#pragma unroll
        for (int j = 0; j < 4; ++j) {
            if (j < nv) {
                t[j]  = tb4[tb0 + j];
                lb[j] = is64 ? tlabw[2 * (tb0 + j)] : tlabw[tb0 + j];
            } else {
                t[j]  = make_float4(0.f, 0.f, 1.f, 1.f);
                lb[j] = 0;
            }
            twd[j] = t[j].z - t[j].x;   // target "width"  (xyxy interp)
            thd[j] = t[j].w - t[j].y;   // target "height"
        }

        float* optr = out + (size_t)row0 * T + tb0;
        int r = 0;
        // two independent rows per iteration: independent dep-chains + batched LDS
        for (; r + 1 < rows_here; r += 2, optr += 2 * T) {
            float4 c0a = srow[r * 3 + 0];
            float4 c1a = srow[r * 3 + 1];
            float  paa = srow[r * 3 + 2].x;
            float4 c0b = srow[r * 3 + 3];
            float4 c1b = srow[r * 3 + 4];
            float  pab = srow[r * 3 + 5].x;

            float4 ra = row_cost4(c0a, c1a, paa, t, twd, thd, lb, sprob + r * C);
            float4 rb = row_cost4(c0b, c1b, pab, t, twd, thd, lb, sprob + (r + 1) * C);

            if (full) {
                *(float4*)optr = ra;
                *(float4*)(optr + T) = rb;
            } else {
#pragma unroll
                for (int j = 0; j < 4; ++j) {
                    if (j < nv) { optr[j] = (&ra.x)[j]; optr[T + j] = (&rb.x)[j]; }
                }
            }
        }
        if (r < rows_here) {
            float4 c0 = srow[r * 3 + 0];
            float4 c1 = srow[r * 3 + 1];
            float  pa = srow[r * 3 + 2].x;
            float4 res = row_cost4(c0, c1, pa, t, twd, thd, lb, sprob + r * C);
            if (full) {
                *(float4*)optr = res;
            } else {
#pragma unroll
                for (int j = 0; j < 4; ++j)
                    if (j < nv) optr[j] = (&res.x)[j];
            }
        }
    }
}

extern "C" void kernel_launch(void* const* d_in, const int* in_sizes, int n_in,
                              void* d_out, int out_size)
{
    const float* logits = (const float*)d_in[0];   // out_labels [B,N,C]
    const float* pboxes = (const float*)d_in[1];   // out_bboxes [B,N,4]
    const int*   tlabw  = (const int*)d_in[2];     // tgt_labels [T] (int32 or int64)
    const float* tboxes = (const float*)d_in[3];   // tgt_bboxes [T,4]
    float* out = (float*)d_out;

    int BN = in_sizes[1] / 4;
    int C  = in_sizes[0] / BN;
    int T  = in_sizes[2];

    int prob_off = (ROWS * C + 3) & ~3;
    size_t smem = (size_t)(prob_off + ROWS * 12) * sizeof(float) + 16;

    int grid = (BN + ROWS - 1) / ROWS;
    matcher_cost_kernel6<<<grid, NTHREADS, smem>>>(logits, pboxes, tlabw, tboxes,
                                                   out, BN, C, T);
}